// round 7
// baseline (speedup 1.0000x reference)
#include <cuda_runtime.h>
#include <cuda_fp16.h>

#define F   128
#define H1  4
#define D   32
#define C1  128
#define NMAX 50176
#define CAP 128         // per-dst edge bucket capacity (Poisson(16): P(>=128) ~ 0)
#define NMCAP (NMAX * CAP)
#define XS  132         // padded smem row stride (floats)

// ---------------- scratch (static device globals; no allocation) -------------
__device__ __align__(16) __half g_h1h[NMAX * C1];   // layer-1 features (fp16)
__device__ __align__(16) float  g_a1 [NMAX * C1];   // layer-1 activated output (fp32)
__device__ __align__(16) float  g_as1[NMAX * H1];
__device__ __align__(16) float  g_ad1[NMAX * H1];
__device__ __align__(16) __half g_h2h[NMAX * D];    // layer-2 features (fp16)
__device__ __align__(16) float  g_exT[4 * NMCAP];   // per-(head, dst, slot) edge weights
__device__ float g_as2[NMAX];
__device__ float g_ad2[NMAX];
__device__ float g_ps [NMAX];   // dot(emb, Wp[0:32])
__device__ float g_pt [NMAX];   // dot(emb, Wp[32:64])
__device__ int   g_cnt[NMAX];
__device__ int   g_col[NMAX * CAP];

// ---------------- helpers ----------------
__device__ __forceinline__ float lrelu(float e) { return fmaxf(e, 0.2f * e); }

__device__ __forceinline__ unsigned long long dup2(float x) {
    unsigned long long a;
    asm("mov.b64 %0, {%1, %1};" : "=l"(a) : "f"(x));
    return a;
}
__device__ __forceinline__ void fma2(unsigned long long& d,
                                     unsigned long long a, unsigned long long b) {
    asm("fma.rn.f32x2 %0, %1, %2, %0;" : "+l"(d) : "l"(a), "l"(b));
}
__device__ __forceinline__ float2 unp(unsigned long long v) {
    float2 r;
    asm("mov.b64 {%0, %1}, %2;" : "=f"(r.x), "=f"(r.y) : "l"(v));
    return r;
}
__device__ __forceinline__ float warp_sum(float v) {
#pragma unroll
    for (int o = 16; o; o >>= 1) v += __shfl_xor_sync(0xffffffffu, v, o);
    return v;
}

// ---------------- K0: zero bucket counters ----------------
__global__ void k_zero(int N) {
    int i = blockIdx.x * blockDim.x + threadIdx.x;
    if (i < N) g_cnt[i] = 0;
}

// ---------------- K1: h1 = x @ W1 (64x128 tile) + fused alpha1 ----------------
__global__ void __launch_bounds__(256) k_gemm1(
    const float* __restrict__ x, const float* __restrict__ W1,
    const float* __restrict__ a_s, const float* __restrict__ a_d, int N) {
    extern __shared__ float sm[];
    float* Ws = sm;               // [128][128]
    float* xs = sm + F * C1;      // [64][XS]
    int tid  = threadIdx.x;
    int row0 = blockIdx.x * 64;

#pragma unroll
    for (int i = 0; i < 16; i++)
        ((float4*)Ws)[i * 256 + tid] = ((const float4*)W1)[i * 256 + tid];
#pragma unroll
    for (int i = 0; i < 8; i++) {
        int lin = i * 256 + tid;
        int k4 = lin & 31, r = lin >> 5;
        int row = row0 + r;
        float4 v = make_float4(0.f, 0.f, 0.f, 0.f);
        if (row < N) v = ((const float4*)x)[row * 32 + k4];
        *(float4*)(xs + r * XS + k4 * 4) = v;
    }
    __syncthreads();

    int tx = tid & 31;            // cols tx*4 .. tx*4+3
    int ty = tid >> 5;            // rows ty*8 .. ty*8+7
    const float* xrow = xs + ty * 8 * XS;
    const float* wcol = Ws + tx * 4;

    unsigned long long acc[8][2];
#pragma unroll
    for (int i = 0; i < 8; i++) { acc[i][0] = 0ull; acc[i][1] = 0ull; }

#pragma unroll 4
    for (int k = 0; k < F; k += 4) {
        unsigned long long wp[4][2];
#pragma unroll
        for (int j = 0; j < 4; j++) {
            wp[j][0] = *(const unsigned long long*)(wcol + (k + j) * C1);
            wp[j][1] = *(const unsigned long long*)(wcol + (k + j) * C1 + 2);
        }
#pragma unroll
        for (int i = 0; i < 8; i++) {
            float4 xv = *(const float4*)(xrow + i * XS + k);
            unsigned long long a0 = dup2(xv.x), a1 = dup2(xv.y),
                               a2 = dup2(xv.z), a3 = dup2(xv.w);
            fma2(acc[i][0], a0, wp[0][0]); fma2(acc[i][1], a0, wp[0][1]);
            fma2(acc[i][0], a1, wp[1][0]); fma2(acc[i][1], a1, wp[1][1]);
            fma2(acc[i][0], a2, wp[2][0]); fma2(acc[i][1], a2, wp[2][1]);
            fma2(acc[i][0], a3, wp[3][0]); fma2(acc[i][1], a3, wp[3][1]);
        }
    }

    float4 sa = ((const float4*)a_s)[tx];
    float4 da = ((const float4*)a_d)[tx];
    int head = tx >> 3;
#pragma unroll
    for (int i = 0; i < 8; i++) {
        int row = row0 + ty * 8 + i;
        float2 lo = unp(acc[i][0]), hi = unp(acc[i][1]);
        float4 h = make_float4(lo.x, lo.y, hi.x, hi.y);
        float ps = h.x * sa.x + h.y * sa.y + h.z * sa.z + h.w * sa.w;
        float pd = h.x * da.x + h.y * da.y + h.z * da.z + h.w * da.w;
#pragma unroll
        for (int o = 4; o; o >>= 1) {
            ps += __shfl_xor_sync(0xffffffffu, ps, o);
            pd += __shfl_xor_sync(0xffffffffu, pd, o);
        }
        if (row < N) {
            __half2 p0 = __floats2half2_rn(h.x, h.y);
            __half2 p1 = __floats2half2_rn(h.z, h.w);
            uint2 pk;
            pk.x = *(unsigned*)&p0;
            pk.y = *(unsigned*)&p1;
            ((uint2*)g_h1h)[row * 32 + tx] = pk;
            if ((tx & 7) == 0) {
                g_as1[row * H1 + head] = ps;
                g_ad1[row * H1 + head] = pd;
            }
        }
    }
}

// ---------------- K2: bucket edges + precompute per-edge softmax weights -----
// thread per edge: computes exp(lrelu(alpha_src+alpha_dst)) for all 4 heads
// (dense lanes: 8x less redundant than doing it warp-wide in agg1).
// Runs AFTER gemm1 (reads g_as1/g_ad1).
__global__ void k_scatter(const int* __restrict__ ei, int E, int N) {
    int i = blockIdx.x * blockDim.x + threadIdx.x;
    int Et = E + N;
    if (i >= Et) return;
    int s, t;
    if (i < E) { s = __ldg(ei + i); t = __ldg(ei + E + i); } else { s = t = i - E; }
    int p = atomicAdd(&g_cnt[t], 1);
    if (p < CAP) {
        int base = t * CAP + p;
        g_col[base] = s;
        float4 as = ((const float4*)g_as1)[s];
        float4 ad = ((const float4*)g_ad1)[t];
        g_exT[0 * NMCAP + base] = __expf(lrelu(as.x + ad.x));
        g_exT[1 * NMCAP + base] = __expf(lrelu(as.y + ad.y));
        g_exT[2 * NMCAP + base] = __expf(lrelu(as.z + ad.z));
        g_exT[3 * NMCAP + base] = __expf(lrelu(as.w + ad.w));
    }
}

// ---------------- K3: layer-1 gather-aggregate + normalize + bias + ELU ------
// warp per dst node; lane owns 4 channels (2x half2), head = lane>>3.
// Edge weights preloaded from g_exT (no exp/lrelu/alpha work here).
__global__ void __launch_bounds__(256) k_agg1(const float* __restrict__ b1, int N) {
    int gid  = blockIdx.x * blockDim.x + threadIdx.x;
    int t    = gid >> 5, lane = gid & 31;
    if (t >= N) return;
    int   h   = lane >> 3;
    int   deg = min(g_cnt[t], CAP);
    const int*   cl  = g_col + t * CAP;
    const float* exb = g_exT + h * NMCAP + t * CAP;

    float4 acc = make_float4(0.f, 0.f, 0.f, 0.f);
    float  sum = 0.f;
    int j = 0;
    for (; j + 2 <= deg; j += 2) {
        int2   ss = *(const int2*)(cl + j);
        float2 ex = *(const float2*)(exb + j);
        uint2 p0 = ((const uint2*)g_h1h)[ss.x * 32 + lane];
        uint2 p1 = ((const uint2*)g_h1h)[ss.y * 32 + lane];
        float2 f0a = __half22float2(*(__half2*)&p0.x);
        float2 f0b = __half22float2(*(__half2*)&p0.y);
        float2 f1a = __half22float2(*(__half2*)&p1.x);
        float2 f1b = __half22float2(*(__half2*)&p1.y);
        acc.x += ex.x * f0a.x + ex.y * f1a.x;
        acc.y += ex.x * f0a.y + ex.y * f1a.y;
        acc.z += ex.x * f0b.x + ex.y * f1b.x;
        acc.w += ex.x * f0b.y + ex.y * f1b.y;
        sum   += ex.x + ex.y;
    }
    if (j < deg) {
        int   s0 = cl[j];
        float e0 = exb[j];
        uint2 p0 = ((const uint2*)g_h1h)[s0 * 32 + lane];
        float2 f0a = __half22float2(*(__half2*)&p0.x);
        float2 f0b = __half22float2(*(__half2*)&p0.y);
        acc.x += e0 * f0a.x; acc.y += e0 * f0a.y;
        acc.z += e0 * f0b.x; acc.w += e0 * f0b.y;
        sum += e0;
    }
    float inv = 1.f / (sum + 1e-16f);
    float4 b = ((const float4*)b1)[lane];
    float4 v;
    v.x = acc.x * inv + b.x; v.y = acc.y * inv + b.y;
    v.z = acc.z * inv + b.z; v.w = acc.w * inv + b.w;
    v.x = v.x > 0.f ? v.x : expm1f(v.x);
    v.y = v.y > 0.f ? v.y : expm1f(v.y);
    v.z = v.z > 0.f ? v.z : expm1f(v.z);
    v.w = v.w > 0.f ? v.w : expm1f(v.w);
    ((float4*)g_a1)[t * 32 + lane] = v;
}

// ---------------- K4: h2 = a1 @ W2 (128x32 tile) + fused alpha2 ----------------
__global__ void __launch_bounds__(256) k_gemm2(
    const float* __restrict__ W2, const float* __restrict__ a_s,
    const float* __restrict__ a_d, int N) {
    extern __shared__ float sm[];
    float* Ws = sm;               // [128][32]
    float* xs = sm + F * D;       // [128][XS]
    int tid  = threadIdx.x;
    int row0 = blockIdx.x * 128;

#pragma unroll
    for (int i = 0; i < 4; i++)
        ((float4*)Ws)[i * 256 + tid] = ((const float4*)W2)[i * 256 + tid];
#pragma unroll
    for (int i = 0; i < 16; i++) {
        int lin = i * 256 + tid;
        int k4 = lin & 31, r = lin >> 5;
        int row = row0 + r;
        float4 v = make_float4(0.f, 0.f, 0.f, 0.f);
        if (row < N) v = ((const float4*)g_a1)[row * 32 + k4];
        *(float4*)(xs + r * XS + k4 * 4) = v;
    }
    __syncthreads();

    int tx = tid & 15;            // col pair c0 = tx*2
    int ty = tid >> 4;            // rows ty*8 .. ty*8+7
    int c0 = tx * 2;
    const float* xrow = xs + ty * 8 * XS;
    const float* wcol = Ws + c0;

    unsigned long long acc[8];
#pragma unroll
    for (int i = 0; i < 8; i++) acc[i] = 0ull;

#pragma unroll 4
    for (int k = 0; k < F; k += 4) {
        unsigned long long wp[4];
#pragma unroll
        for (int j = 0; j < 4; j++)
            wp[j] = *(const unsigned long long*)(wcol + (k + j) * D);
#pragma unroll
        for (int i = 0; i < 8; i++) {
            float4 xv = *(const float4*)(xrow + i * XS + k);
            fma2(acc[i], dup2(xv.x), wp[0]);
            fma2(acc[i], dup2(xv.y), wp[1]);
            fma2(acc[i], dup2(xv.z), wp[2]);
            fma2(acc[i], dup2(xv.w), wp[3]);
        }
    }

    float2 sa = *(const float2*)(a_s + c0);
    float2 da = *(const float2*)(a_d + c0);
#pragma unroll
    for (int i = 0; i < 8; i++) {
        int row = row0 + ty * 8 + i;
        float2 hv = unp(acc[i]);
        float ps = hv.x * sa.x + hv.y * sa.y;
        float pd = hv.x * da.x + hv.y * da.y;
#pragma unroll
        for (int o = 8; o; o >>= 1) {   // reduce within 16-lane half-warp
            ps += __shfl_xor_sync(0xffffffffu, ps, o);
            pd += __shfl_xor_sync(0xffffffffu, pd, o);
        }
        if (row < N) {
            __half2 p = __floats2half2_rn(hv.x, hv.y);
            ((unsigned*)g_h2h)[row * 16 + tx] = *(unsigned*)&p;
            if (tx == 0) { g_as2[row] = ps; g_ad2[row] = pd; }
        }
    }
}

// ---------------- K5: layer-2 gather-aggregate + fused rating projection -----
__global__ void __launch_bounds__(256) k_agg2(
    const float* __restrict__ b2, const float* __restrict__ Wp, int N) {
    int gid  = blockIdx.x * blockDim.x + threadIdx.x;
    int t    = gid >> 5, lane = gid & 31;
    if (t >= N) return;
    float adt = g_ad2[t];
    int   deg = min(g_cnt[t], CAP);
    const int* cl = g_col + t * CAP;

    float acc = 0.f, sum = 0.f;
    int j = 0;
    for (; j + 2 <= deg; j += 2) {
        int2  ss  = *(const int2*)(cl + j);
        float as0 = g_as2[ss.x];
        float as1 = g_as2[ss.y];
        float h0  = __half2float(g_h2h[ss.x * D + lane]);
        float h1  = __half2float(g_h2h[ss.y * D + lane]);
        float e0 = __expf(lrelu(as0 + adt));
        float e1 = __expf(lrelu(as1 + adt));
        acc += e0 * h0 + e1 * h1;
        sum += e0 + e1;
    }
    if (j < deg) {
        int s0 = cl[j];
        float e0 = __expf(lrelu(g_as2[s0] + adt));
        acc += e0 * __half2float(g_h2h[s0 * D + lane]);
        sum += e0;
    }
    float v = acc / (sum + 1e-16f) + b2[lane];
    float ps = warp_sum(v * Wp[lane]);
    float pt = warp_sum(v * Wp[D + lane]);
    if (lane == 0) { g_ps[t] = ps; g_pt[t] = pt; }
}

// ---------------- K6: edge rating = ps[src] + pt[dst] + bp (thread/edge) -----
__global__ void __launch_bounds__(256) k_pred(
    const int* __restrict__ ei, const float* __restrict__ bp,
    float* __restrict__ out, int E) {
    int e = blockIdx.x * blockDim.x + threadIdx.x;
    if (e >= E) return;
    int s = __ldg(ei + e), t = __ldg(ei + E + e);
    out[e] = g_ps[s] + g_pt[t] + bp[0];
}

// ---------------- launch ----------------
extern "C" void kernel_launch(void* const* d_in, const int* in_sizes, int n_in,
                              void* d_out, int out_size) {
    const float* x   = (const float*)d_in[0];
    const int*   ei  = (const int*)  d_in[1];
    const float* W1  = (const float*)d_in[2];
    const float* as1 = (const float*)d_in[3];
    const float* ad1 = (const float*)d_in[4];
    const float* b1  = (const float*)d_in[5];
    const float* W2  = (const float*)d_in[6];
    const float* as2 = (const float*)d_in[7];
    const float* ad2 = (const float*)d_in[8];
    const float* b2  = (const float*)d_in[9];
    const float* Wp  = (const float*)d_in[10];
    const float* bp  = (const float*)d_in[11];
    float*       out = (float*)d_out;

    int N  = in_sizes[0] / F;
    int E  = in_sizes[1] / 2;
    int Et = E + N;
    if (N > NMAX) return;

    int smem1 = (F * C1 + 64 * XS) * (int)sizeof(float);    // 99328
    int smem2 = (F * D + 128 * XS) * (int)sizeof(float);    // 83968
    cudaFuncSetAttribute(k_gemm1, cudaFuncAttributeMaxDynamicSharedMemorySize, smem1);
    cudaFuncSetAttribute(k_gemm2, cudaFuncAttributeMaxDynamicSharedMemorySize, smem2);

    k_zero   <<<(N + 255) / 256, 256>>>(N);
    k_gemm1  <<<(N + 63) / 64, 256, smem1>>>(x, W1, as1, ad1, N);
    k_scatter<<<(Et + 255) / 256, 256>>>(ei, E, N);
    k_agg1   <<<(N * 32 + 255) / 256, 256>>>(b1, N);
    k_gemm2  <<<(N + 127) / 128, 256, smem2>>>(W2, as2, ad2, N);
    k_agg2   <<<(N * 32 + 255) / 256, 256>>>(b2, Wp, N);
    k_pred   <<<(E + 255) / 256, 256>>>(ei, bp, out, E);
}

// round 8
// speedup vs baseline: 1.1702x; 1.1702x over previous
#include <cuda_runtime.h>
#include <cuda_fp16.h>

#define F   128
#define H1  4
#define D   32
#define C1  128
#define NMAX 50176
#define CAP 128         // per-dst edge bucket capacity (Poisson(16): P(>=128) ~ 0)
#define XS  132         // padded smem row stride (floats)

// ---------------- scratch (static device globals; no allocation) -------------
__device__ __align__(16) __half g_h1h[NMAX * C1];   // layer-1 features (fp16)
__device__ __align__(16) float  g_a1 [NMAX * C1];   // layer-1 activated output (fp32)
__device__ __align__(16) float  g_as1[NMAX * H1];
__device__ __align__(16) float  g_ad1[NMAX * H1];
__device__ __align__(16) __half g_h2h[NMAX * D];    // layer-2 features (fp16)
__device__ float g_as2[NMAX];
__device__ float g_ad2[NMAX];
__device__ float g_ps [NMAX];   // dot(emb, Wp[0:32])
__device__ float g_pt [NMAX];   // dot(emb, Wp[32:64])
__device__ int   g_cnt[NMAX];
__device__ int   g_col[NMAX * CAP];

// ---------------- helpers ----------------
__device__ __forceinline__ float lrelu(float e) { return fmaxf(e, 0.2f * e); }

__device__ __forceinline__ unsigned long long dup2(float x) {
    unsigned long long a;
    asm("mov.b64 %0, {%1, %1};" : "=l"(a) : "f"(x));
    return a;
}
__device__ __forceinline__ void fma2(unsigned long long& d,
                                     unsigned long long a, unsigned long long b) {
    asm("fma.rn.f32x2 %0, %1, %2, %0;" : "+l"(d) : "l"(a), "l"(b));
}
__device__ __forceinline__ float2 unp(unsigned long long v) {
    float2 r;
    asm("mov.b64 {%0, %1}, %2;" : "=f"(r.x), "=f"(r.y) : "l"(v));
    return r;
}
__device__ __forceinline__ float warp_sum(float v) {
#pragma unroll
    for (int o = 16; o; o >>= 1) v += __shfl_xor_sync(0xffffffffu, v, o);
    return v;
}

// ---------------- K0: zero bucket counters ----------------
__global__ void k_zero(int N) {
    int i = blockIdx.x * blockDim.x + threadIdx.x;
    if (i < N) g_cnt[i] = 0;
}

// ---------------- K1: bucket edges by destination (CSR-lite, light) ----------
__global__ void k_scatter(const int* __restrict__ ei, int E, int N) {
    int i = blockIdx.x * blockDim.x + threadIdx.x;
    int Et = E + N;
    if (i >= Et) return;
    int s, t;
    if (i < E) { s = __ldg(ei + i); t = __ldg(ei + E + i); } else { s = t = i - E; }
    int p = atomicAdd(&g_cnt[t], 1);
    if (p < CAP) g_col[t * CAP + p] = s;
}

// ---------------- K2: h1 = x @ W1 (64x128 tile) + fused alpha1 ----------------
__global__ void __launch_bounds__(256) k_gemm1(
    const float* __restrict__ x, const float* __restrict__ W1,
    const float* __restrict__ a_s, const float* __restrict__ a_d, int N) {
    extern __shared__ float sm[];
    float* Ws = sm;               // [128][128]
    float* xs = sm + F * C1;      // [64][XS]
    int tid  = threadIdx.x;
    int row0 = blockIdx.x * 64;

#pragma unroll
    for (int i = 0; i < 16; i++)
        ((float4*)Ws)[i * 256 + tid] = ((const float4*)W1)[i * 256 + tid];
#pragma unroll
    for (int i = 0; i < 8; i++) {
        int lin = i * 256 + tid;
        int k4 = lin & 31, r = lin >> 5;
        int row = row0 + r;
        float4 v = make_float4(0.f, 0.f, 0.f, 0.f);
        if (row < N) v = ((const float4*)x)[row * 32 + k4];
        *(float4*)(xs + r * XS + k4 * 4) = v;
    }
    __syncthreads();

    int tx = tid & 31;            // cols tx*4 .. tx*4+3
    int ty = tid >> 5;            // rows ty*8 .. ty*8+7
    const float* xrow = xs + ty * 8 * XS;
    const float* wcol = Ws + tx * 4;

    unsigned long long acc[8][2];
#pragma unroll
    for (int i = 0; i < 8; i++) { acc[i][0] = 0ull; acc[i][1] = 0ull; }

#pragma unroll 4
    for (int k = 0; k < F; k += 4) {
        unsigned long long wp[4][2];
#pragma unroll
        for (int j = 0; j < 4; j++) {
            wp[j][0] = *(const unsigned long long*)(wcol + (k + j) * C1);
            wp[j][1] = *(const unsigned long long*)(wcol + (k + j) * C1 + 2);
        }
#pragma unroll
        for (int i = 0; i < 8; i++) {
            float4 xv = *(const float4*)(xrow + i * XS + k);
            unsigned long long a0 = dup2(xv.x), a1 = dup2(xv.y),
                               a2 = dup2(xv.z), a3 = dup2(xv.w);
            fma2(acc[i][0], a0, wp[0][0]); fma2(acc[i][1], a0, wp[0][1]);
            fma2(acc[i][0], a1, wp[1][0]); fma2(acc[i][1], a1, wp[1][1]);
            fma2(acc[i][0], a2, wp[2][0]); fma2(acc[i][1], a2, wp[2][1]);
            fma2(acc[i][0], a3, wp[3][0]); fma2(acc[i][1], a3, wp[3][1]);
        }
    }

    float4 sa = ((const float4*)a_s)[tx];
    float4 da = ((const float4*)a_d)[tx];
    int head = tx >> 3;
#pragma unroll
    for (int i = 0; i < 8; i++) {
        int row = row0 + ty * 8 + i;
        float2 lo = unp(acc[i][0]), hi = unp(acc[i][1]);
        float4 h = make_float4(lo.x, lo.y, hi.x, hi.y);
        float ps = h.x * sa.x + h.y * sa.y + h.z * sa.z + h.w * sa.w;
        float pd = h.x * da.x + h.y * da.y + h.z * da.z + h.w * da.w;
#pragma unroll
        for (int o = 4; o; o >>= 1) {
            ps += __shfl_xor_sync(0xffffffffu, ps, o);
            pd += __shfl_xor_sync(0xffffffffu, pd, o);
        }
        if (row < N) {
            __half2 p0 = __floats2half2_rn(h.x, h.y);
            __half2 p1 = __floats2half2_rn(h.z, h.w);
            uint2 pk;
            pk.x = *(unsigned*)&p0;
            pk.y = *(unsigned*)&p1;
            ((uint2*)g_h1h)[row * 32 + tx] = pk;
            if ((tx & 7) == 0) {
                g_as1[row * H1 + head] = ps;
                g_ad1[row * H1 + head] = pd;
            }
        }
    }
}

// ---------------- K3: layer-1 gather-aggregate + normalize + bias + ELU ------
// warp per dst node; lane owns 4 channels, head = lane>>3, sub = lane&7.
// Per 8-edge chunk: one DENSE exp per lane (8 edges x 4 heads = 32 lanes),
// then shfl-broadcast (s_j, e_j) into the channel-aggregation loop.
__global__ void __launch_bounds__(256) k_agg1(const float* __restrict__ b1, int N) {
    int gid  = blockIdx.x * blockDim.x + threadIdx.x;
    int t    = gid >> 5, lane = gid & 31;
    if (t >= N) return;
    int   head = lane >> 3;
    int   sub  = lane & 7;
    int   hsel = lane & 24;       // head*8: shfl source base for e
    float adt  = g_ad1[t * H1 + head];
    int   deg  = min(g_cnt[t], CAP);
    const int* cl = g_col + t * CAP;

    float4 acc = make_float4(0.f, 0.f, 0.f, 0.f);
    float  sum = 0.f;
    for (int j0 = 0; j0 < deg; j0 += 8) {
        int  idx   = j0 + sub;
        bool valid = idx < deg;
        int  s8 = cl[valid ? idx : (deg - 1)];
        float as = g_as1[s8 * H1 + head];
        float e  = valid ? __expf(lrelu(as + adt)) : 0.f;
        int m = min(8, deg - j0);
        for (int j = 0; j < m; j++) {
            int   sj = __shfl_sync(0xffffffffu, s8, j);
            float ej = __shfl_sync(0xffffffffu, e, hsel | j);
            uint2 p  = ((const uint2*)g_h1h)[sj * 32 + lane];
            float2 fa = __half22float2(*(__half2*)&p.x);
            float2 fb = __half22float2(*(__half2*)&p.y);
            acc.x += ej * fa.x; acc.y += ej * fa.y;
            acc.z += ej * fb.x; acc.w += ej * fb.y;
            sum   += ej;
        }
    }
    float inv = 1.f / (sum + 1e-16f);
    float4 b = ((const float4*)b1)[lane];
    float4 v;
    v.x = acc.x * inv + b.x; v.y = acc.y * inv + b.y;
    v.z = acc.z * inv + b.z; v.w = acc.w * inv + b.w;
    v.x = v.x > 0.f ? v.x : expm1f(v.x);
    v.y = v.y > 0.f ? v.y : expm1f(v.y);
    v.z = v.z > 0.f ? v.z : expm1f(v.z);
    v.w = v.w > 0.f ? v.w : expm1f(v.w);
    ((float4*)g_a1)[t * 32 + lane] = v;
}

// ---------------- K4: h2 = a1 @ W2 (128x32 tile) + fused alpha2 ----------------
__global__ void __launch_bounds__(256) k_gemm2(
    const float* __restrict__ W2, const float* __restrict__ a_s,
    const float* __restrict__ a_d, int N) {
    extern __shared__ float sm[];
    float* Ws = sm;               // [128][32]
    float* xs = sm + F * D;       // [128][XS]
    int tid  = threadIdx.x;
    int row0 = blockIdx.x * 128;

#pragma unroll
    for (int i = 0; i < 4; i++)
        ((float4*)Ws)[i * 256 + tid] = ((const float4*)W2)[i * 256 + tid];
#pragma unroll
    for (int i = 0; i < 16; i++) {
        int lin = i * 256 + tid;
        int k4 = lin & 31, r = lin >> 5;
        int row = row0 + r;
        float4 v = make_float4(0.f, 0.f, 0.f, 0.f);
        if (row < N) v = ((const float4*)g_a1)[row * 32 + k4];
        *(float4*)(xs + r * XS + k4 * 4) = v;
    }
    __syncthreads();

    int tx = tid & 15;            // col pair c0 = tx*2
    int ty = tid >> 4;            // rows ty*8 .. ty*8+7
    int c0 = tx * 2;
    const float* xrow = xs + ty * 8 * XS;
    const float* wcol = Ws + c0;

    unsigned long long acc[8];
#pragma unroll
    for (int i = 0; i < 8; i++) acc[i] = 0ull;

#pragma unroll 4
    for (int k = 0; k < F; k += 4) {
        unsigned long long wp[4];
#pragma unroll
        for (int j = 0; j < 4; j++)
            wp[j] = *(const unsigned long long*)(wcol + (k + j) * D);
#pragma unroll
        for (int i = 0; i < 8; i++) {
            float4 xv = *(const float4*)(xrow + i * XS + k);
            fma2(acc[i], dup2(xv.x), wp[0]);
            fma2(acc[i], dup2(xv.y), wp[1]);
            fma2(acc[i], dup2(xv.z), wp[2]);
            fma2(acc[i], dup2(xv.w), wp[3]);
        }
    }

    float2 sa = *(const float2*)(a_s + c0);
    float2 da = *(const float2*)(a_d + c0);
#pragma unroll
    for (int i = 0; i < 8; i++) {
        int row = row0 + ty * 8 + i;
        float2 hv = unp(acc[i]);
        float ps = hv.x * sa.x + hv.y * sa.y;
        float pd = hv.x * da.x + hv.y * da.y;
#pragma unroll
        for (int o = 8; o; o >>= 1) {   // reduce within 16-lane half-warp
            ps += __shfl_xor_sync(0xffffffffu, ps, o);
            pd += __shfl_xor_sync(0xffffffffu, pd, o);
        }
        if (row < N) {
            __half2 p = __floats2half2_rn(hv.x, hv.y);
            ((unsigned*)g_h2h)[row * 16 + tx] = *(unsigned*)&p;
            if (tx == 0) { g_as2[row] = ps; g_ad2[row] = pd; }
        }
    }
}

// ---------------- K5: layer-2 gather-aggregate + fused rating projection -----
// warp per dst node; lane = channel. Per 32-edge chunk: one dense exp per
// lane, then shfl-broadcast into the aggregation loop.
__global__ void __launch_bounds__(256) k_agg2(
    const float* __restrict__ b2, const float* __restrict__ Wp, int N) {
    int gid  = blockIdx.x * blockDim.x + threadIdx.x;
    int t    = gid >> 5, lane = gid & 31;
    if (t >= N) return;
    float adt = g_ad2[t];
    int   deg = min(g_cnt[t], CAP);
    const int* cl = g_col + t * CAP;

    float acc = 0.f, sum = 0.f;
    for (int j0 = 0; j0 < deg; j0 += 32) {
        int  idx   = j0 + lane;
        bool valid = idx < deg;
        int  s32 = cl[valid ? idx : (deg - 1)];
        float e = valid ? __expf(lrelu(g_as2[s32] + adt)) : 0.f;
        int m = min(32, deg - j0);
        for (int j = 0; j < m; j++) {
            int   sj = __shfl_sync(0xffffffffu, s32, j);
            float ej = __shfl_sync(0xffffffffu, e, j);
            acc += ej * __half2float(g_h2h[sj * D + lane]);
            sum += ej;
        }
    }
    float v = acc / (sum + 1e-16f) + b2[lane];
    float ps = warp_sum(v * Wp[lane]);
    float pt = warp_sum(v * Wp[D + lane]);
    if (lane == 0) { g_ps[t] = ps; g_pt[t] = pt; }
}

// ---------------- K6: edge rating = ps[src] + pt[dst] + bp (thread/edge) -----
__global__ void __launch_bounds__(256) k_pred(
    const int* __restrict__ ei, const float* __restrict__ bp,
    float* __restrict__ out, int E) {
    int e = blockIdx.x * blockDim.x + threadIdx.x;
    if (e >= E) return;
    int s = __ldg(ei + e), t = __ldg(ei + E + e);
    out[e] = g_ps[s] + g_pt[t] + bp[0];
}

// ---------------- launch ----------------
extern "C" void kernel_launch(void* const* d_in, const int* in_sizes, int n_in,
                              void* d_out, int out_size) {
    const float* x   = (const float*)d_in[0];
    const int*   ei  = (const int*)  d_in[1];
    const float* W1  = (const float*)d_in[2];
    const float* as1 = (const float*)d_in[3];
    const float* ad1 = (const float*)d_in[4];
    const float* b1  = (const float*)d_in[5];
    const float* W2  = (const float*)d_in[6];
    const float* as2 = (const float*)d_in[7];
    const float* ad2 = (const float*)d_in[8];
    const float* b2  = (const float*)d_in[9];
    const float* Wp  = (const float*)d_in[10];
    const float* bp  = (const float*)d_in[11];
    float*       out = (float*)d_out;

    int N  = in_sizes[0] / F;
    int E  = in_sizes[1] / 2;
    int Et = E + N;
    if (N > NMAX) return;

    int smem1 = (F * C1 + 64 * XS) * (int)sizeof(float);    // 99328
    int smem2 = (F * D + 128 * XS) * (int)sizeof(float);    // 83968
    cudaFuncSetAttribute(k_gemm1, cudaFuncAttributeMaxDynamicSharedMemorySize, smem1);
    cudaFuncSetAttribute(k_gemm2, cudaFuncAttributeMaxDynamicSharedMemorySize, smem2);

    k_zero   <<<(N + 255) / 256, 256>>>(N);
    k_scatter<<<(Et + 255) / 256, 256>>>(ei, E, N);
    k_gemm1  <<<(N + 63) / 64, 256, smem1>>>(x, W1, as1, ad1, N);
    k_agg1   <<<(N * 32 + 255) / 256, 256>>>(b1, N);
    k_gemm2  <<<(N + 127) / 128, 256, smem2>>>(W2, as2, ad2, N);
    k_agg2   <<<(N * 32 + 255) / 256, 256>>>(b2, Wp, N);
    k_pred   <<<(E + 255) / 256, 256>>>(ei, bp, out, E);
}

// round 9
// speedup vs baseline: 1.3076x; 1.1174x over previous
#include <cuda_runtime.h>
#include <cuda_fp16.h>

#define F   128
#define H1  4
#define D   32
#define C1  128
#define NMAX 50176
#define CAP 128         // per-dst edge bucket capacity (Poisson(16): P(>=128) ~ 0)
#define XS  132         // padded smem stride for gemm2 (floats)
#define XT  136         // padded smem stride for gemm1 tf32 tiles (words)

// ---------------- scratch (static device globals; no allocation) -------------
__device__ __align__(16) __half g_h1h[NMAX * C1];   // layer-1 features (fp16)
__device__ __align__(16) float  g_a1 [NMAX * C1];   // layer-1 activated output (fp32)
__device__ __align__(16) float  g_as1[NMAX * H1];
__device__ __align__(16) float  g_ad1[NMAX * H1];
__device__ __align__(16) __half g_h2h[NMAX * D];    // layer-2 features (fp16)
__device__ float g_as2[NMAX];
__device__ float g_ad2[NMAX];
__device__ float g_ps [NMAX];   // dot(emb, Wp[0:32])
__device__ float g_pt [NMAX];   // dot(emb, Wp[32:64])
__device__ int   g_cnt[NMAX];
__device__ __align__(16) int g_col[NMAX * CAP];

// ---------------- helpers ----------------
__device__ __forceinline__ float lrelu(float e) { return fmaxf(e, 0.2f * e); }

__device__ __forceinline__ unsigned tf32(float v) {
    unsigned r;
    asm("cvt.rna.tf32.f32 %0, %1;" : "=r"(r) : "f"(v));
    return r;
}
__device__ __forceinline__ void mma_tf32(float c[4], unsigned a0, unsigned a1,
                                         unsigned a2, unsigned a3,
                                         unsigned b0, unsigned b1) {
    asm volatile("mma.sync.aligned.m16n8k8.row.col.f32.tf32.tf32.f32 "
                 "{%0,%1,%2,%3}, {%4,%5,%6,%7}, {%8,%9}, {%0,%1,%2,%3};"
                 : "+f"(c[0]), "+f"(c[1]), "+f"(c[2]), "+f"(c[3])
                 : "r"(a0), "r"(a1), "r"(a2), "r"(a3), "r"(b0), "r"(b1));
}
__device__ __forceinline__ unsigned long long dup2(float x) {
    unsigned long long a;
    asm("mov.b64 %0, {%1, %1};" : "=l"(a) : "f"(x));
    return a;
}
__device__ __forceinline__ void fma2(unsigned long long& d,
                                     unsigned long long a, unsigned long long b) {
    asm("fma.rn.f32x2 %0, %1, %2, %0;" : "+l"(d) : "l"(a), "l"(b));
}
__device__ __forceinline__ float2 unp(unsigned long long v) {
    float2 r;
    asm("mov.b64 {%0, %1}, %2;" : "=f"(r.x), "=f"(r.y) : "l"(v));
    return r;
}
__device__ __forceinline__ float warp_sum(float v) {
#pragma unroll
    for (int o = 16; o; o >>= 1) v += __shfl_xor_sync(0xffffffffu, v, o);
    return v;
}

// ---------------- K0: zero bucket counters ----------------
__global__ void k_zero(int N) {
    int i = blockIdx.x * blockDim.x + threadIdx.x;
    if (i < N) g_cnt[i] = 0;
}

// ---------------- K1: bucket edges by destination (CSR-lite) ----------------
__global__ void k_scatter(const int* __restrict__ ei, int E, int N) {
    int i = blockIdx.x * blockDim.x + threadIdx.x;
    int Et = E + N;
    if (i >= Et) return;
    int s, t;
    if (i < E) { s = __ldg(ei + i); t = __ldg(ei + E + i); } else { s = t = i - E; }
    int p = atomicAdd(&g_cnt[t], 1);
    if (p < CAP) g_col[t * CAP + p] = s;
}

// ---------------- K2: h1 = x @ W1 via tf32 mma.sync (128-row block) ----------
// 256 thr = 8 warps; warp w computes rows w*16..w*16+15 x all 128 cols.
// W1 + x tile staged in smem as tf32, XT=136 padding (conflict-free frags).
__global__ void __launch_bounds__(256) k_gemm1(
    const float* __restrict__ x, const float* __restrict__ W1,
    const float* __restrict__ a_s, const float* __restrict__ a_d, int N) {
    extern __shared__ unsigned smu[];
    unsigned* Wt = smu;              // [128][XT] tf32
    unsigned* Xt = smu + 128 * XT;   // [128][XT] tf32; reused as fp32 C after loop
    int tid  = threadIdx.x;
    int row0 = blockIdx.x * 128;

    // stage W1 (128x128) as tf32
#pragma unroll
    for (int i = 0; i < 16; i++) {
        int lin = i * 256 + tid;              // float4 index
        int k = lin >> 5, n4 = lin & 31;
        float4 w = ((const float4*)W1)[lin];
        uint4 q = make_uint4(tf32(w.x), tf32(w.y), tf32(w.z), tf32(w.w));
        *(uint4*)(Wt + k * XT + n4 * 4) = q;
    }
    // stage x rows as tf32
#pragma unroll
    for (int i = 0; i < 16; i++) {
        int lin = i * 256 + tid;
        int r = lin >> 5, k4 = lin & 31;
        int row = row0 + r;
        float4 v = make_float4(0.f, 0.f, 0.f, 0.f);
        if (row < N) v = ((const float4*)x)[row * 32 + k4];
        uint4 q = make_uint4(tf32(v.x), tf32(v.y), tf32(v.z), tf32(v.w));
        *(uint4*)(Xt + r * XT + k4 * 4) = q;
    }
    __syncthreads();

    int lane = tid & 31, warp = tid >> 5;
    int g = lane >> 2, t4 = lane & 3;
    int wrow = warp * 16;

    float c[16][4];
#pragma unroll
    for (int n = 0; n < 16; n++) { c[n][0] = c[n][1] = c[n][2] = c[n][3] = 0.f; }

#pragma unroll 2
    for (int k0 = 0; k0 < 128; k0 += 8) {
        unsigned a0 = Xt[(wrow + g)     * XT + k0 + t4];
        unsigned a1 = Xt[(wrow + g + 8) * XT + k0 + t4];
        unsigned a2 = Xt[(wrow + g)     * XT + k0 + t4 + 4];
        unsigned a3 = Xt[(wrow + g + 8) * XT + k0 + t4 + 4];
#pragma unroll
        for (int n = 0; n < 16; n++) {
            unsigned b0 = Wt[(k0 + t4)     * XT + n * 8 + g];
            unsigned b1 = Wt[(k0 + t4 + 4) * XT + n * 8 + g];
            mma_tf32(c[n], a0, a1, a2, a3, b0, b1);
        }
    }
    __syncthreads();                // all warps done reading Xt

    // write C frags to smem (reuse Xt) for the clean epilogue layout
    float* Cs = (float*)Xt;
#pragma unroll
    for (int n = 0; n < 16; n++) {
        *(float2*)(Cs + (wrow + g)     * XT + n * 8 + t4 * 2) = make_float2(c[n][0], c[n][1]);
        *(float2*)(Cs + (wrow + g + 8) * XT + n * 8 + t4 * 2) = make_float2(c[n][2], c[n][3]);
    }
    __syncthreads();

    // epilogue: tx = 4-col group, ty covers 16 rows; alpha + fp16 store
    int tx = tid & 31, ty = tid >> 5;
    float4 sa = ((const float4*)a_s)[tx];
    float4 da = ((const float4*)a_d)[tx];
    int head = tx >> 3;
#pragma unroll
    for (int i = 0; i < 16; i++) {
        int r   = ty * 16 + i;
        int row = row0 + r;
        float4 h = *(const float4*)(Cs + r * XT + tx * 4);
        float ps = h.x * sa.x + h.y * sa.y + h.z * sa.z + h.w * sa.w;
        float pd = h.x * da.x + h.y * da.y + h.z * da.z + h.w * da.w;
#pragma unroll
        for (int o = 4; o; o >>= 1) {
            ps += __shfl_xor_sync(0xffffffffu, ps, o);
            pd += __shfl_xor_sync(0xffffffffu, pd, o);
        }
        if (row < N) {
            __half2 p0 = __floats2half2_rn(h.x, h.y);
            __half2 p1 = __floats2half2_rn(h.z, h.w);
            uint2 pk;
            pk.x = *(unsigned*)&p0;
            pk.y = *(unsigned*)&p1;
            ((uint2*)g_h1h)[row * 32 + tx] = pk;
            if ((tx & 7) == 0) {
                g_as1[row * H1 + head] = ps;
                g_ad1[row * H1 + head] = pd;
            }
        }
    }
}

// ---------------- K3: layer-1 gather-aggregate (R6 form, 4-way unroll) -------
__global__ void __launch_bounds__(256) k_agg1(const float* __restrict__ b1, int N) {
    int gid  = blockIdx.x * blockDim.x + threadIdx.x;
    int t    = gid >> 5, lane = gid & 31;
    if (t >= N) return;
    int   h   = lane >> 3;
    float adt = g_ad1[t * H1 + h];
    int   deg = min(g_cnt[t], CAP);
    const int* cl = g_col + t * CAP;

    float4 acc = make_float4(0.f, 0.f, 0.f, 0.f);
    float  sum = 0.f;
    int j = 0;
    for (; j + 4 <= deg; j += 4) {
        int4  ss = *(const int4*)(cl + j);
        float a0 = g_as1[ss.x * H1 + h];
        float a1 = g_as1[ss.y * H1 + h];
        float a2 = g_as1[ss.z * H1 + h];
        float a3 = g_as1[ss.w * H1 + h];
        uint2 p0 = ((const uint2*)g_h1h)[ss.x * 32 + lane];
        uint2 p1 = ((const uint2*)g_h1h)[ss.y * 32 + lane];
        uint2 p2 = ((const uint2*)g_h1h)[ss.z * 32 + lane];
        uint2 p3 = ((const uint2*)g_h1h)[ss.w * 32 + lane];
        float e0 = __expf(lrelu(a0 + adt));
        float e1 = __expf(lrelu(a1 + adt));
        float e2 = __expf(lrelu(a2 + adt));
        float e3 = __expf(lrelu(a3 + adt));
        float2 f0a = __half22float2(*(__half2*)&p0.x), f0b = __half22float2(*(__half2*)&p0.y);
        float2 f1a = __half22float2(*(__half2*)&p1.x), f1b = __half22float2(*(__half2*)&p1.y);
        float2 f2a = __half22float2(*(__half2*)&p2.x), f2b = __half22float2(*(__half2*)&p2.y);
        float2 f3a = __half22float2(*(__half2*)&p3.x), f3b = __half22float2(*(__half2*)&p3.y);
        acc.x += e0 * f0a.x + e1 * f1a.x + e2 * f2a.x + e3 * f3a.x;
        acc.y += e0 * f0a.y + e1 * f1a.y + e2 * f2a.y + e3 * f3a.y;
        acc.z += e0 * f0b.x + e1 * f1b.x + e2 * f2b.x + e3 * f3b.x;
        acc.w += e0 * f0b.y + e1 * f1b.y + e2 * f2b.y + e3 * f3b.y;
        sum   += (e0 + e1) + (e2 + e3);
    }
    for (; j < deg; j++) {
        int   s0 = cl[j];
        float e0 = __expf(lrelu(g_as1[s0 * H1 + h] + adt));
        uint2 p0 = ((const uint2*)g_h1h)[s0 * 32 + lane];
        float2 f0a = __half22float2(*(__half2*)&p0.x);
        float2 f0b = __half22float2(*(__half2*)&p0.y);
        acc.x += e0 * f0a.x; acc.y += e0 * f0a.y;
        acc.z += e0 * f0b.x; acc.w += e0 * f0b.y;
        sum += e0;
    }
    float inv = 1.f / (sum + 1e-16f);
    float4 b = ((const float4*)b1)[lane];
    float4 v;
    v.x = acc.x * inv + b.x; v.y = acc.y * inv + b.y;
    v.z = acc.z * inv + b.z; v.w = acc.w * inv + b.w;
    v.x = v.x > 0.f ? v.x : expm1f(v.x);
    v.y = v.y > 0.f ? v.y : expm1f(v.y);
    v.z = v.z > 0.f ? v.z : expm1f(v.z);
    v.w = v.w > 0.f ? v.w : expm1f(v.w);
    ((float4*)g_a1)[t * 32 + lane] = v;
}

// ---------------- K4: h2 = a1 @ W2 (128x32 tile) + fused alpha2 ----------------
__global__ void __launch_bounds__(256) k_gemm2(
    const float* __restrict__ W2, const float* __restrict__ a_s,
    const float* __restrict__ a_d, int N) {
    extern __shared__ float sm[];
    float* Ws = sm;               // [128][32]
    float* xs = sm + F * D;       // [128][XS]
    int tid  = threadIdx.x;
    int row0 = blockIdx.x * 128;

#pragma unroll
    for (int i = 0; i < 4; i++)
        ((float4*)Ws)[i * 256 + tid] = ((const float4*)W2)[i * 256 + tid];
#pragma unroll
    for (int i = 0; i < 16; i++) {
        int lin = i * 256 + tid;
        int k4 = lin & 31, r = lin >> 5;
        int row = row0 + r;
        float4 v = make_float4(0.f, 0.f, 0.f, 0.f);
        if (row < N) v = ((const float4*)g_a1)[row * 32 + k4];
        *(float4*)(xs + r * XS + k4 * 4) = v;
    }
    __syncthreads();

    int tx = tid & 15;            // col pair c0 = tx*2
    int ty = tid >> 4;            // rows ty*8 .. ty*8+7
    int c0 = tx * 2;
    const float* xrow = xs + ty * 8 * XS;
    const float* wcol = Ws + c0;

    unsigned long long acc[8];
#pragma unroll
    for (int i = 0; i < 8; i++) acc[i] = 0ull;

#pragma unroll 4
    for (int k = 0; k < F; k += 4) {
        unsigned long long wp[4];
#pragma unroll
        for (int j = 0; j < 4; j++)
            wp[j] = *(const unsigned long long*)(wcol + (k + j) * D);
#pragma unroll
        for (int i = 0; i < 8; i++) {
            float4 xv = *(const float4*)(xrow + i * XS + k);
            fma2(acc[i], dup2(xv.x), wp[0]);
            fma2(acc[i], dup2(xv.y), wp[1]);
            fma2(acc[i], dup2(xv.z), wp[2]);
            fma2(acc[i], dup2(xv.w), wp[3]);
        }
    }

    float2 sa = *(const float2*)(a_s + c0);
    float2 da = *(const float2*)(a_d + c0);
#pragma unroll
    for (int i = 0; i < 8; i++) {
        int row = row0 + ty * 8 + i;
        float2 hv = unp(acc[i]);
        float ps = hv.x * sa.x + hv.y * sa.y;
        float pd = hv.x * da.x + hv.y * da.y;
#pragma unroll
        for (int o = 8; o; o >>= 1) {
            ps += __shfl_xor_sync(0xffffffffu, ps, o);
            pd += __shfl_xor_sync(0xffffffffu, pd, o);
        }
        if (row < N) {
            __half2 p = __floats2half2_rn(hv.x, hv.y);
            ((unsigned*)g_h2h)[row * 16 + tx] = *(unsigned*)&p;
            if (tx == 0) { g_as2[row] = ps; g_ad2[row] = pd; }
        }
    }
}

// ---------------- K5: layer-2 gather-aggregate + fused rating projection -----
// warp per dst node; dense exp per 32-edge chunk + shfl broadcast (R8, works).
__global__ void __launch_bounds__(256) k_agg2(
    const float* __restrict__ b2, const float* __restrict__ Wp, int N) {
    int gid  = blockIdx.x * blockDim.x + threadIdx.x;
    int t    = gid >> 5, lane = gid & 31;
    if (t >= N) return;
    float adt = g_ad2[t];
    int   deg = min(g_cnt[t], CAP);
    const int* cl = g_col + t * CAP;

    float acc = 0.f, sum = 0.f;
    for (int j0 = 0; j0 < deg; j0 += 32) {
        int  idx   = j0 + lane;
        bool valid = idx < deg;
        int  s32 = cl[valid ? idx : (deg - 1)];
        float e = valid ? __expf(lrelu(g_as2[s32] + adt)) : 0.f;
        int m = min(32, deg - j0);
        for (int j = 0; j < m; j++) {
            int   sj = __shfl_sync(0xffffffffu, s32, j);
            float ej = __shfl_sync(0xffffffffu, e, j);
            acc += ej * __half2float(g_h2h[sj * D + lane]);
            sum += ej;
        }
    }
    float v = acc / (sum + 1e-16f) + b2[lane];
    float ps = warp_sum(v * Wp[lane]);
    float pt = warp_sum(v * Wp[D + lane]);
    if (lane == 0) { g_ps[t] = ps; g_pt[t] = pt; }
}

// ---------------- K6: edge rating = ps[src] + pt[dst] + bp (thread/edge) -----
__global__ void __launch_bounds__(256) k_pred(
    const int* __restrict__ ei, const float* __restrict__ bp,
    float* __restrict__ out, int E) {
    int e = blockIdx.x * blockDim.x + threadIdx.x;
    if (e >= E) return;
    int s = __ldg(ei + e), t = __ldg(ei + E + e);
    out[e] = g_ps[s] + g_pt[t] + bp[0];
}

// ---------------- launch ----------------
extern "C" void kernel_launch(void* const* d_in, const int* in_sizes, int n_in,
                              void* d_out, int out_size) {
    const float* x   = (const float*)d_in[0];
    const int*   ei  = (const int*)  d_in[1];
    const float* W1  = (const float*)d_in[2];
    const float* as1 = (const float*)d_in[3];
    const float* ad1 = (const float*)d_in[4];
    const float* b1  = (const float*)d_in[5];
    const float* W2  = (const float*)d_in[6];
    const float* as2 = (const float*)d_in[7];
    const float* ad2 = (const float*)d_in[8];
    const float* b2  = (const float*)d_in[9];
    const float* Wp  = (const float*)d_in[10];
    const float* bp  = (const float*)d_in[11];
    float*       out = (float*)d_out;

    int N  = in_sizes[0] / F;
    int E  = in_sizes[1] / 2;
    int Et = E + N;
    if (N > NMAX) return;

    int smem1 = 2 * 128 * XT * (int)sizeof(unsigned);   // 139264
    int smem2 = (F * D + 128 * XS) * (int)sizeof(float);
    cudaFuncSetAttribute(k_gemm1, cudaFuncAttributeMaxDynamicSharedMemorySize, smem1);
    cudaFuncSetAttribute(k_gemm2, cudaFuncAttributeMaxDynamicSharedMemorySize, smem2);

    k_zero   <<<(N + 255) / 256, 256>>>(N);
    k_scatter<<<(Et + 255) / 256, 256>>>(ei, E, N);
    k_gemm1  <<<(N + 127) / 128, 256, smem1>>>(x, W1, as1, ad1, N);
    k_agg1   <<<(N * 32 + 255) / 256, 256>>>(b1, N);
    k_gemm2  <<<(N + 127) / 128, 256, smem2>>>(W2, as2, ad2, N);
    k_agg2   <<<(N * 32 + 255) / 256, 256>>>(b2, Wp, N);
    k_pred   <<<(E + 255) / 256, 256>>>(ei, bp, out, E);
}

// round 10
// speedup vs baseline: 1.3475x; 1.0305x over previous
#include <cuda_runtime.h>
#include <cuda_fp16.h>

#define F   128
#define H1  4
#define D   32
#define C1  128
#define NMAX 50176
#define CAP 128         // per-dst edge bucket capacity (Poisson(16): P(>=128) ~ 0)
#define XS  132         // padded smem stride for gemm2 (floats)
#define XT  136         // padded smem stride for gemm1 tf32 tiles (words)

// ---------------- scratch (static device globals; no allocation) -------------
__device__ __align__(16) __half g_h1h[NMAX * C1];   // layer-1 features (fp16)
__device__ __align__(16) float  g_a1 [NMAX * C1];   // layer-1 activated output (fp32)
__device__ __align__(16) float  g_as1[NMAX * H1];
__device__ __align__(16) float  g_ad1[NMAX * H1];
__device__ __align__(16) __half g_h2h[NMAX * D];    // layer-2 features (fp16)
__device__ float g_as2[NMAX];
__device__ float g_ad2[NMAX];
__device__ float g_ps [NMAX];   // dot(emb, Wp[0:32])
__device__ float g_pt [NMAX];   // dot(emb, Wp[32:64])
__device__ int   g_cnt[NMAX];
__device__ __align__(16) int g_col[NMAX * CAP];

// ---------------- helpers ----------------
__device__ __forceinline__ float lrelu(float e) { return fmaxf(e, 0.2f * e); }

__device__ __forceinline__ unsigned tf32(float v) {
    unsigned r;
    asm("cvt.rna.tf32.f32 %0, %1;" : "=r"(r) : "f"(v));
    return r;
}
__device__ __forceinline__ void mma_tf32(float c[4], unsigned a0, unsigned a1,
                                         unsigned a2, unsigned a3,
                                         unsigned b0, unsigned b1) {
    asm volatile("mma.sync.aligned.m16n8k8.row.col.f32.tf32.tf32.f32 "
                 "{%0,%1,%2,%3}, {%4,%5,%6,%7}, {%8,%9}, {%0,%1,%2,%3};"
                 : "+f"(c[0]), "+f"(c[1]), "+f"(c[2]), "+f"(c[3])
                 : "r"(a0), "r"(a1), "r"(a2), "r"(a3), "r"(b0), "r"(b1));
}
__device__ __forceinline__ unsigned long long dup2(float x) {
    unsigned long long a;
    asm("mov.b64 %0, {%1, %1};" : "=l"(a) : "f"(x));
    return a;
}
__device__ __forceinline__ void fma2(unsigned long long& d,
                                     unsigned long long a, unsigned long long b) {
    asm("fma.rn.f32x2 %0, %1, %2, %0;" : "+l"(d) : "l"(a), "l"(b));
}
__device__ __forceinline__ float2 unp(unsigned long long v) {
    float2 r;
    asm("mov.b64 {%0, %1}, %2;" : "=f"(r.x), "=f"(r.y) : "l"(v));
    return r;
}
__device__ __forceinline__ float warp_sum(float v) {
#pragma unroll
    for (int o = 16; o; o >>= 1) v += __shfl_xor_sync(0xffffffffu, v, o);
    return v;
}

// ---------------- K0: zero bucket counters ----------------
__global__ void k_zero(int N) {
    int i = blockIdx.x * blockDim.x + threadIdx.x;
    if (i < N) g_cnt[i] = 0;
}

// ---------------- K1: bucket edges by destination (CSR-lite) ----------------
__global__ void k_scatter(const int* __restrict__ ei, int E, int N) {
    int i = blockIdx.x * blockDim.x + threadIdx.x;
    int Et = E + N;
    if (i >= Et) return;
    int s, t;
    if (i < E) { s = __ldg(ei + i); t = __ldg(ei + E + i); } else { s = t = i - E; }
    int p = atomicAdd(&g_cnt[t], 1);
    if (p < CAP) g_col[t * CAP + p] = s;
}

// ---------------- K2: h1 = x @ W1 via tf32 mma.sync (128-row block) ----------
__global__ void __launch_bounds__(256) k_gemm1(
    const float* __restrict__ x, const float* __restrict__ W1,
    const float* __restrict__ a_s, const float* __restrict__ a_d, int N) {
    extern __shared__ unsigned smu[];
    unsigned* Wt = smu;              // [128][XT] tf32
    unsigned* Xt = smu + 128 * XT;   // [128][XT] tf32; reused as fp32 C after loop
    int tid  = threadIdx.x;
    int row0 = blockIdx.x * 128;

#pragma unroll
    for (int i = 0; i < 16; i++) {
        int lin = i * 256 + tid;              // float4 index
        int k = lin >> 5, n4 = lin & 31;
        float4 w = ((const float4*)W1)[lin];
        uint4 q = make_uint4(tf32(w.x), tf32(w.y), tf32(w.z), tf32(w.w));
        *(uint4*)(Wt + k * XT + n4 * 4) = q;
    }
#pragma unroll
    for (int i = 0; i < 16; i++) {
        int lin = i * 256 + tid;
        int r = lin >> 5, k4 = lin & 31;
        int row = row0 + r;
        float4 v = make_float4(0.f, 0.f, 0.f, 0.f);
        if (row < N) v = ((const float4*)x)[row * 32 + k4];
        uint4 q = make_uint4(tf32(v.x), tf32(v.y), tf32(v.z), tf32(v.w));
        *(uint4*)(Xt + r * XT + k4 * 4) = q;
    }
    __syncthreads();

    int lane = tid & 31, warp = tid >> 5;
    int g = lane >> 2, t4 = lane & 3;
    int wrow = warp * 16;

    float c[16][4];
#pragma unroll
    for (int n = 0; n < 16; n++) { c[n][0] = c[n][1] = c[n][2] = c[n][3] = 0.f; }

#pragma unroll 2
    for (int k0 = 0; k0 < 128; k0 += 8) {
        unsigned a0 = Xt[(wrow + g)     * XT + k0 + t4];
        unsigned a1 = Xt[(wrow + g + 8) * XT + k0 + t4];
        unsigned a2 = Xt[(wrow + g)     * XT + k0 + t4 + 4];
        unsigned a3 = Xt[(wrow + g + 8) * XT + k0 + t4 + 4];
#pragma unroll
        for (int n = 0; n < 16; n++) {
            unsigned b0 = Wt[(k0 + t4)     * XT + n * 8 + g];
            unsigned b1 = Wt[(k0 + t4 + 4) * XT + n * 8 + g];
            mma_tf32(c[n], a0, a1, a2, a3, b0, b1);
        }
    }
    __syncthreads();

    float* Cs = (float*)Xt;
#pragma unroll
    for (int n = 0; n < 16; n++) {
        *(float2*)(Cs + (wrow + g)     * XT + n * 8 + t4 * 2) = make_float2(c[n][0], c[n][1]);
        *(float2*)(Cs + (wrow + g + 8) * XT + n * 8 + t4 * 2) = make_float2(c[n][2], c[n][3]);
    }
    __syncthreads();

    int tx = tid & 31, ty = tid >> 5;
    float4 sa = ((const float4*)a_s)[tx];
    float4 da = ((const float4*)a_d)[tx];
    int head = tx >> 3;
#pragma unroll
    for (int i = 0; i < 16; i++) {
        int r   = ty * 16 + i;
        int row = row0 + r;
        float4 h = *(const float4*)(Cs + r * XT + tx * 4);
        float ps = h.x * sa.x + h.y * sa.y + h.z * sa.z + h.w * sa.w;
        float pd = h.x * da.x + h.y * da.y + h.z * da.z + h.w * da.w;
#pragma unroll
        for (int o = 4; o; o >>= 1) {
            ps += __shfl_xor_sync(0xffffffffu, ps, o);
            pd += __shfl_xor_sync(0xffffffffu, pd, o);
        }
        if (row < N) {
            __half2 p0 = __floats2half2_rn(h.x, h.y);
            __half2 p1 = __floats2half2_rn(h.z, h.w);
            uint2 pk;
            pk.x = *(unsigned*)&p0;
            pk.y = *(unsigned*)&p1;
            ((uint2*)g_h1h)[row * 32 + tx] = pk;
            if ((tx & 7) == 0) {
                g_as1[row * H1 + head] = ps;
                g_ad1[row * H1 + head] = pd;
            }
        }
    }
}

// ---------------- K3: layer-1 gather-aggregate, smem dense-exp ---------------
// warp per dst node (8 nodes/block). Phase 1: dense lanes compute edge exps
// into exs[warp][head][slot] (head-major => contiguous slots). Phase 2: lane
// owns 4 channels; loads 4 edge weights per LDS.128 (broadcast, no conflicts).
__global__ void __launch_bounds__(256) k_agg1(const float* __restrict__ b1, int N) {
    __shared__ float exs[8][H1][CAP];   // 16 KB
    int warp = threadIdx.x >> 5, lane = threadIdx.x & 31;
    int t = blockIdx.x * 8 + warp;
    if (t >= N) return;
    int head = lane >> 3, sub = lane & 7;
    int deg = min(g_cnt[t], CAP);
    const int* cl = g_col + t * CAP;
    float adt = g_ad1[t * H1 + head];

    for (int j0 = 0; j0 < deg; j0 += 8) {
        int idx = j0 + sub;
        if (idx < deg) {
            int s = cl[idx];
            exs[warp][head][idx] = __expf(lrelu(g_as1[s * H1 + head] + adt));
        }
    }
    __syncwarp();

    const float* eh = exs[warp][head];
    float4 acc = make_float4(0.f, 0.f, 0.f, 0.f);
    float  sum = 0.f;
    int j = 0;
    for (; j + 4 <= deg; j += 4) {
        int4   ss = *(const int4*)(cl + j);
        float4 ev = *(const float4*)(eh + j);
        uint2 p0 = ((const uint2*)g_h1h)[ss.x * 32 + lane];
        uint2 p1 = ((const uint2*)g_h1h)[ss.y * 32 + lane];
        uint2 p2 = ((const uint2*)g_h1h)[ss.z * 32 + lane];
        uint2 p3 = ((const uint2*)g_h1h)[ss.w * 32 + lane];
        float2 f0a = __half22float2(*(__half2*)&p0.x), f0b = __half22float2(*(__half2*)&p0.y);
        float2 f1a = __half22float2(*(__half2*)&p1.x), f1b = __half22float2(*(__half2*)&p1.y);
        float2 f2a = __half22float2(*(__half2*)&p2.x), f2b = __half22float2(*(__half2*)&p2.y);
        float2 f3a = __half22float2(*(__half2*)&p3.x), f3b = __half22float2(*(__half2*)&p3.y);
        acc.x += ev.x * f0a.x + ev.y * f1a.x + ev.z * f2a.x + ev.w * f3a.x;
        acc.y += ev.x * f0a.y + ev.y * f1a.y + ev.z * f2a.y + ev.w * f3a.y;
        acc.z += ev.x * f0b.x + ev.y * f1b.x + ev.z * f2b.x + ev.w * f3b.x;
        acc.w += ev.x * f0b.y + ev.y * f1b.y + ev.z * f2b.y + ev.w * f3b.y;
        sum   += (ev.x + ev.y) + (ev.z + ev.w);
    }
    for (; j < deg; j++) {
        int   s0 = cl[j];
        float e0 = eh[j];
        uint2 p0 = ((const uint2*)g_h1h)[s0 * 32 + lane];
        float2 f0a = __half22float2(*(__half2*)&p0.x);
        float2 f0b = __half22float2(*(__half2*)&p0.y);
        acc.x += e0 * f0a.x; acc.y += e0 * f0a.y;
        acc.z += e0 * f0b.x; acc.w += e0 * f0b.y;
        sum += e0;
    }
    float inv = 1.f / (sum + 1e-16f);
    float4 b = ((const float4*)b1)[lane];
    float4 v;
    v.x = acc.x * inv + b.x; v.y = acc.y * inv + b.y;
    v.z = acc.z * inv + b.z; v.w = acc.w * inv + b.w;
    v.x = v.x > 0.f ? v.x : expm1f(v.x);
    v.y = v.y > 0.f ? v.y : expm1f(v.y);
    v.z = v.z > 0.f ? v.z : expm1f(v.z);
    v.w = v.w > 0.f ? v.w : expm1f(v.w);
    ((float4*)g_a1)[t * 32 + lane] = v;
}

// ---------------- K4: h2 = a1 @ W2 (128x32 tile) + fused alpha2 ----------------
__global__ void __launch_bounds__(256) k_gemm2(
    const float* __restrict__ W2, const float* __restrict__ a_s,
    const float* __restrict__ a_d, int N) {
    extern __shared__ float sm[];
    float* Ws = sm;               // [128][32]
    float* xs = sm + F * D;       // [128][XS]
    int tid  = threadIdx.x;
    int row0 = blockIdx.x * 128;

#pragma unroll
    for (int i = 0; i < 4; i++)
        ((float4*)Ws)[i * 256 + tid] = ((const float4*)W2)[i * 256 + tid];
#pragma unroll
    for (int i = 0; i < 16; i++) {
        int lin = i * 256 + tid;
        int k4 = lin & 31, r = lin >> 5;
        int row = row0 + r;
        float4 v = make_float4(0.f, 0.f, 0.f, 0.f);
        if (row < N) v = ((const float4*)g_a1)[row * 32 + k4];
        *(float4*)(xs + r * XS + k4 * 4) = v;
    }
    __syncthreads();

    int tx = tid & 15;            // col pair c0 = tx*2
    int ty = tid >> 4;            // rows ty*8 .. ty*8+7
    int c0 = tx * 2;
    const float* xrow = xs + ty * 8 * XS;
    const float* wcol = Ws + c0;

    unsigned long long acc[8];
#pragma unroll
    for (int i = 0; i < 8; i++) acc[i] = 0ull;

#pragma unroll 4
    for (int k = 0; k < F; k += 4) {
        unsigned long long wp[4];
#pragma unroll
        for (int j = 0; j < 4; j++)
            wp[j] = *(const unsigned long long*)(wcol + (k + j) * D);
#pragma unroll
        for (int i = 0; i < 8; i++) {
            float4 xv = *(const float4*)(xrow + i * XS + k);
            fma2(acc[i], dup2(xv.x), wp[0]);
            fma2(acc[i], dup2(xv.y), wp[1]);
            fma2(acc[i], dup2(xv.z), wp[2]);
            fma2(acc[i], dup2(xv.w), wp[3]);
        }
    }

    float2 sa = *(const float2*)(a_s + c0);
    float2 da = *(const float2*)(a_d + c0);
#pragma unroll
    for (int i = 0; i < 8; i++) {
        int row = row0 + ty * 8 + i;
        float2 hv = unp(acc[i]);
        float ps = hv.x * sa.x + hv.y * sa.y;
        float pd = hv.x * da.x + hv.y * da.y;
#pragma unroll
        for (int o = 8; o; o >>= 1) {
            ps += __shfl_xor_sync(0xffffffffu, ps, o);
            pd += __shfl_xor_sync(0xffffffffu, pd, o);
        }
        if (row < N) {
            __half2 p = __floats2half2_rn(hv.x, hv.y);
            ((unsigned*)g_h2h)[row * 16 + tx] = *(unsigned*)&p;
            if (tx == 0) { g_as2[row] = ps; g_ad2[row] = pd; }
        }
    }
}

// ---------------- K5: layer-2 gather-aggregate + fused rating projection -----
__global__ void __launch_bounds__(256) k_agg2(
    const float* __restrict__ b2, const float* __restrict__ Wp, int N) {
    int gid  = blockIdx.x * blockDim.x + threadIdx.x;
    int t    = gid >> 5, lane = gid & 31;
    if (t >= N) return;
    float adt = g_ad2[t];
    int   deg = min(g_cnt[t], CAP);
    const int* cl = g_col + t * CAP;

    float acc = 0.f, sum = 0.f;
    for (int j0 = 0; j0 < deg; j0 += 32) {
        int  idx   = j0 + lane;
        bool valid = idx < deg;
        int  s32 = cl[valid ? idx : (deg - 1)];
        float e = valid ? __expf(lrelu(g_as2[s32] + adt)) : 0.f;
        int m = min(32, deg - j0);
        for (int j = 0; j < m; j++) {
            int   sj = __shfl_sync(0xffffffffu, s32, j);
            float ej = __shfl_sync(0xffffffffu, e, j);
            acc += ej * __half2float(g_h2h[sj * D + lane]);
            sum += ej;
        }
    }
    float v = acc / (sum + 1e-16f) + b2[lane];
    float ps = warp_sum(v * Wp[lane]);
    float pt = warp_sum(v * Wp[D + lane]);
    if (lane == 0) { g_ps[t] = ps; g_pt[t] = pt; }
}

// ---------------- K6: edge rating = ps[src] + pt[dst] + bp (thread/edge) -----
__global__ void __launch_bounds__(256) k_pred(
    const int* __restrict__ ei, const float* __restrict__ bp,
    float* __restrict__ out, int E) {
    int e = blockIdx.x * blockDim.x + threadIdx.x;
    if (e >= E) return;
    int s = __ldg(ei + e), t = __ldg(ei + E + e);
    out[e] = g_ps[s] + g_pt[t] + bp[0];
}

// ---------------- launch ----------------
extern "C" void kernel_launch(void* const* d_in, const int* in_sizes, int n_in,
                              void* d_out, int out_size) {
    const float* x   = (const float*)d_in[0];
    const int*   ei  = (const int*)  d_in[1];
    const float* W1  = (const float*)d_in[2];
    const float* as1 = (const float*)d_in[3];
    const float* ad1 = (const float*)d_in[4];
    const float* b1  = (const float*)d_in[5];
    const float* W2  = (const float*)d_in[6];
    const float* as2 = (const float*)d_in[7];
    const float* ad2 = (const float*)d_in[8];
    const float* b2  = (const float*)d_in[9];
    const float* Wp  = (const float*)d_in[10];
    const float* bp  = (const float*)d_in[11];
    float*       out = (float*)d_out;

    int N  = in_sizes[0] / F;
    int E  = in_sizes[1] / 2;
    int Et = E + N;
    if (N > NMAX) return;

    int smem1 = 2 * 128 * XT * (int)sizeof(unsigned);   // 139264
    int smem2 = (F * D + 128 * XS) * (int)sizeof(float);
    cudaFuncSetAttribute(k_gemm1, cudaFuncAttributeMaxDynamicSharedMemorySize, smem1);
    cudaFuncSetAttribute(k_gemm2, cudaFuncAttributeMaxDynamicSharedMemorySize, smem2);

    k_zero   <<<(N + 255) / 256, 256>>>(N);
    k_scatter<<<(Et + 255) / 256, 256>>>(ei, E, N);
    k_gemm1  <<<(N + 127) / 128, 256, smem1>>>(x, W1, as1, ad1, N);
    k_agg1   <<<(N + 7) / 8, 256>>>(b1, N);
    k_gemm2  <<<(N + 127) / 128, 256, smem2>>>(W2, as2, ad2, N);
    k_agg2   <<<(N * 32 + 255) / 256, 256>>>(b2, Wp, N);
    k_pred   <<<(E + 255) / 256, 256>>>(ei, bp, out, E);
}